// round 8
// baseline (speedup 1.0000x reference)
#include <cuda_runtime.h>

// Problem constants
#define I_ 3
#define H_ 2048
#define O_ 2
#define R_ 2
#define S_ 4
#define G_ 7
#define B_ 32
#define T_ 512
#define ALPHA_ 0.2f
#define DECAY_ 0.8f
#define NSTD_ 0.05f

#define NTHREADS 512
#define NWARPS (NTHREADS / 32)   // 16
#define EPT 4                    // 512*4 = 2048 = H
#define NPAIR (EPT / 2)

typedef unsigned long long u64;

// ---- f32x2 packed helpers ----
__device__ __forceinline__ u64 pack2(float lo, float hi) {
    u64 r; asm("mov.b64 %0, {%1,%2};" : "=l"(r) : "f"(lo), "f"(hi)); return r;
}
__device__ __forceinline__ void unpack2(u64 v, float& lo, float& hi) {
    asm("mov.b64 {%0,%1}, %2;" : "=f"(lo), "=f"(hi) : "l"(v));
}
__device__ __forceinline__ u64 fma2(u64 a, u64 b, u64 c) {
    u64 d; asm("fma.rn.f32x2 %0, %1, %2, %3;" : "=l"(d) : "l"(a), "l"(b), "l"(c)); return d;
}
__device__ __forceinline__ u64 mul2(u64 a, u64 b) {
    u64 d; asm("mul.rn.f32x2 %0, %1, %2;" : "=l"(d) : "l"(a), "l"(b)); return d;
}
__device__ __forceinline__ u64 add2(u64 a, u64 b) {
    u64 d; asm("add.rn.f32x2 %0, %1, %2;" : "=l"(d) : "l"(a), "l"(b)); return d;
}
__device__ __forceinline__ float ex2f(float x) {
    float y; asm("ex2.approx.f32 %0, %1;" : "=f"(y) : "f"(x)); return y;
}
__device__ __forceinline__ float rcpf(float x) {
    float y; asm("rcp.approx.f32 %0, %1;" : "=f"(y) : "f"(x)); return y;
}
// packed tanh: 1 - 2/(1+exp(2x)) — same precision class as R4-R7 (rel_err 6e-6)
__device__ __forceinline__ u64 tanh2(u64 hp, u64 c_2log2e, u64 c_one, u64 c_neg2) {
    u64 y = mul2(hp, c_2log2e);
    float y0, y1; unpack2(y, y0, y1);
    float e0 = ex2f(y0), e1 = ex2f(y1);
    u64 dp = add2(pack2(e0, e1), c_one);
    float d0, d1; unpack2(dp, d0, d1);
    float r0 = rcpf(d0), r1 = rcpf(d1);
    return fma2(pack2(r0, r1), c_neg2, c_one);
}

__global__ __launch_bounds__(NTHREADS, 1)
void lowrank_rnn_kernel(const float* __restrict__ input,   // (B,T,I)
                        const float* __restrict__ noise,   // (B,T,H)
                        const float* __restrict__ wi,      // (I,S,G)
                        const float* __restrict__ unitwi,  // (I,S,1)
                        const float* __restrict__ m,       // (R,S,G)
                        const float* __restrict__ n,       // (R,S,G)
                        const float* __restrict__ unitm,   // (R,S,1)
                        const float* __restrict__ unitn,   // (R,S,1)
                        const float* __restrict__ wo,      // (O,S,G)
                        const float* __restrict__ h0,      // (S,G)
                        const float* __restrict__ unith0,  // (S,1)
                        const float* __restrict__ bias,    // (S,1)
                        const float* __restrict__ gb,      // (G,H)
                        const float* __restrict__ uv,      // (1,H)
                        const float* __restrict__ sup,     // (S,H)
                        float* __restrict__ out)           // out(B,T,O) ++ traj(B,T,H)
{
    const int b    = blockIdx.x;
    const int tid  = threadIdx.x;
    const int lane = tid & 31;
    const unsigned FULL = 0xffffffffu;

    // Triple-buffered channel totals, accumulated by smem atomics.
    // Slot order within a buffer: [0]=n0, [1]=wo0, [2]=n1, [3]=wo1
    __shared__ __align__(16) float s_tot[3][4];

    if (tid < 12) ((float*)s_tot)[tid] = 0.f;

    // ------------------------------------------------------------------
    // Phase 1: per-element effective weights (one-time), then pack.
    // ------------------------------------------------------------------
    float f_h[EPT];
    float f_m0[EPT], f_m1[EPT], f_n0[EPT], f_n1[EPT];
    float f_wo0[EPT], f_wo1[EPT], f_bias[EPT];
    float f_wi0[EPT], f_wi1[EPT], f_wi2[EPT];

#pragma unroll
    for (int e = 0; e < EPT; e++) {
        const int hidx = tid * EPT + e;
        float gvec[G_];
#pragma unroll
        for (int g = 0; g < G_; g++) gvec[g] = gb[g * H_ + hidx];
        const float uvh = uv[hidx];

        float awi0 = 0.f, awi1 = 0.f, awi2 = 0.f;
        float am0 = 0.f, am1 = 0.f, an0 = 0.f, an1 = 0.f;
        float awo0 = 0.f, awo1 = 0.f, ah0 = 0.f, ab = 0.f;

#pragma unroll
        for (int s = 0; s < S_; s++) {
            const float su = sup[s * H_ + hidx];

            float d0 = 0.f, d1 = 0.f, d2 = 0.f;
#pragma unroll
            for (int g = 0; g < G_; g++) {
                d0 += wi[(0 * S_ + s) * G_ + g] * gvec[g];
                d1 += wi[(1 * S_ + s) * G_ + g] * gvec[g];
                d2 += wi[(2 * S_ + s) * G_ + g] * gvec[g];
            }
            awi0 += (d0 + unitwi[0 * S_ + s] * uvh) * su;
            awi1 += (d1 + unitwi[1 * S_ + s] * uvh) * su;
            awi2 += (d2 + unitwi[2 * S_ + s] * uvh) * su;

            float dm0 = 0.f, dm1 = 0.f, dn0 = 0.f, dn1 = 0.f;
#pragma unroll
            for (int g = 0; g < G_; g++) {
                dm0 += m[(0 * S_ + s) * G_ + g] * gvec[g];
                dm1 += m[(1 * S_ + s) * G_ + g] * gvec[g];
                dn0 += n[(0 * S_ + s) * G_ + g] * gvec[g];
                dn1 += n[(1 * S_ + s) * G_ + g] * gvec[g];
            }
            am0 += (dm0 + unitm[0 * S_ + s] * uvh) * su;
            am1 += (dm1 + unitm[1 * S_ + s] * uvh) * su;
            an0 += (dn0 + unitn[0 * S_ + s] * uvh) * su;
            an1 += (dn1 + unitn[1 * S_ + s] * uvh) * su;

            float do0 = 0.f, do1 = 0.f, dh = 0.f;
#pragma unroll
            for (int g = 0; g < G_; g++) {
                do0 += wo[(0 * S_ + s) * G_ + g] * gvec[g];
                do1 += wo[(1 * S_ + s) * G_ + g] * gvec[g];
                dh  += h0[s * G_ + g] * gvec[g];
            }
            awo0 += do0 * su;
            awo1 += do1 * su;
            ah0  += dh * su + unith0[s] * uvh * su;
            ab   += bias[s] * uvh * su;
        }
        f_h[e]   = ah0;
        f_m0[e]  = ALPHA_ * am0;  f_m1[e]  = ALPHA_ * am1;
        f_n0[e]  = an0;           f_n1[e]  = an1;
        f_wo0[e] = awo0;          f_wo1[e] = awo1;
        f_bias[e] = ab;
        f_wi0[e] = ALPHA_ * awi0; f_wi1[e] = ALPHA_ * awi1;
        f_wi2[e] = ALPHA_ * awi2;
    }

    // Packed state/constants
    u64 hpack[NPAIR];
    u64 p_m0[NPAIR], p_m1[NPAIR];
    u64 p_wi0[NPAIR], p_wi1[NPAIR], p_wi2[NPAIR], p_bias[NPAIR];
    u64 p_n01[EPT], p_wo01[EPT];
#pragma unroll
    for (int p = 0; p < NPAIR; p++) {
        hpack[p]  = pack2(f_h[2 * p],   f_h[2 * p + 1]);
        p_m0[p]   = pack2(f_m0[2 * p],  f_m0[2 * p + 1]);
        p_m1[p]   = pack2(f_m1[2 * p],  f_m1[2 * p + 1]);
        p_wi0[p]  = pack2(f_wi0[2 * p], f_wi0[2 * p + 1]);
        p_wi1[p]  = pack2(f_wi1[2 * p], f_wi1[2 * p + 1]);
        p_wi2[p]  = pack2(f_wi2[2 * p], f_wi2[2 * p + 1]);
        p_bias[p] = pack2(f_bias[2 * p], f_bias[2 * p + 1]);
    }
#pragma unroll
    for (int e = 0; e < EPT; e++) {
        p_n01[e]  = pack2(f_n0[e],  f_n1[e]);
        p_wo01[e] = pack2(f_wo0[e], f_wo1[e]);
    }
    const u64 C_DECAY2  = pack2(DECAY_, DECAY_);
    const u64 C_NSTD2   = pack2(NSTD_, NSTD_);
    const u64 C_2LOG2E2 = pack2(2.8853900817779268f, 2.8853900817779268f);
    const u64 C_ONE2    = pack2(1.0f, 1.0f);
    const u64 C_NEG22   = pack2(-2.0f, -2.0f);

    __syncthreads();   // totals zeroed before first atomics

    // ------------------------------------------------------------------
    // Phase 2: recurrence.
    //   Loop-top invariant: prA=(Σr·n0, Σr·n1), prB=(Σr·wo0, Σr·wo1) of
    //   r_t = tanh(h_t); hpack = h_t.
    //   Per iter: folded warp-reduce -> 4 lanes; lanes 0-3 atomicAdd into
    //   s_tot[t%3]; barrier; one LDS.128 gives (Sn0, o0, Sn1, o1) to all.
    // ------------------------------------------------------------------
    const float* zb = noise + (size_t)b * T_ * H_;
    const float* xb = input + (size_t)b * T_ * I_;
    float* outp  = out + (size_t)b * T_ * O_;
    float* trajp = out + (size_t)B_ * T_ * O_ + (size_t)b * T_ * H_;

    // Initial pr from r0 = tanh(h0)
    u64 prA = pack2(0.f, 0.f), prB = pack2(0.f, 0.f);
#pragma unroll
    for (int p = 0; p < NPAIR; p++) {
        u64 th = tanh2(hpack[p], C_2LOG2E2, C_ONE2, C_NEG22);
        float r0, r1; unpack2(th, r0, r1);
        prA = fma2(pack2(r0, r0), p_n01[2 * p],      prA);
        prB = fma2(pack2(r0, r0), p_wo01[2 * p],     prB);
        prA = fma2(pack2(r1, r1), p_n01[2 * p + 1],  prA);
        prB = fma2(pack2(r1, r1), p_wo01[2 * p + 1], prB);
    }

    // Prefetch noise / input two steps ahead
    float4 z0 = *(const float4*)(zb + 0 * (size_t)H_ + tid * 4);
    float4 z1 = *(const float4*)(zb + 1 * (size_t)H_ + tid * 4);
    float xA0 = xb[0], xA1 = xb[1], xA2 = xb[2];
    float xB0 = xb[3], xB1 = xb[4], xB2 = xb[5];

    int buf = 0;       // t % 3
    int buf2 = 2;      // (t+2) % 3

    for (int t = 0; t < T_; t++) {
        // ---- stage A: warp-level folded reduce (6 SHFL) ----
        float v;
        {
            float px, py, pz, pw;
            unpack2(prA, px, py);
            unpack2(prB, pz, pw);
            const bool k1 = !(lane & 1);
            float sA = k1 ? pz : px;
            float rA = __shfl_xor_sync(FULL, sA, 1);
            float v0 = (k1 ? px : pz) + rA;
            float sB = k1 ? pw : py;
            float rB = __shfl_xor_sync(FULL, sB, 1);
            float v1 = (k1 ? py : pw) + rB;
            const bool k2 = !(lane & 2);
            float sC = k2 ? v1 : v0;
            float rC = __shfl_xor_sync(FULL, sC, 2);
            v = (k2 ? v0 : v1) + rC;
            v += __shfl_xor_sync(FULL, v, 4);
            v += __shfl_xor_sync(FULL, v, 8);
            v += __shfl_xor_sync(FULL, v, 16);
        }
        // lane&3: 0 -> n0, 1 -> wo0, 2 -> n1, 3 -> wo1 (warp totals)
        if (lane < 4) atomicAdd(&s_tot[buf][lane], v);

        // ---- shadow: traj store, prefetch, full hb ----
        if (t > 0) {
            float h0f, h1f, h2f, h3f;
            unpack2(hpack[0], h0f, h1f);
            unpack2(hpack[1], h2f, h3f);
            *(float4*)(trajp + (size_t)(t - 1) * H_ + tid * 4) =
                make_float4(h0f, h1f, h2f, h3f);
        }
        const int tp = (t + 2 < T_) ? (t + 2) : (T_ - 1);
        float4 z2 = *(const float4*)(zb + (size_t)tp * H_ + tid * 4);
        const float xC0 = xb[tp * I_ + 0];
        const float xC1 = xb[tp * I_ + 1];
        const float xC2 = xb[tp * I_ + 2];

        u64 hb[NPAIR];
        {
            u64 xA0p = pack2(xA0, xA0);
            u64 xA1p = pack2(xA1, xA1);
            u64 xA2p = pack2(xA2, xA2);
            u64 zp0 = pack2(z0.x, z0.y);
            u64 zp1 = pack2(z0.z, z0.w);
            hb[0] = fma2(hpack[0], C_DECAY2, p_bias[0]);
            hb[0] = fma2(zp0, C_NSTD2, hb[0]);
            hb[1] = fma2(hpack[1], C_DECAY2, p_bias[1]);
            hb[1] = fma2(zp1, C_NSTD2, hb[1]);
#pragma unroll
            for (int p = 0; p < NPAIR; p++) {
                hb[p] = fma2(xA0p, p_wi0[p], hb[p]);
                hb[p] = fma2(xA1p, p_wi1[p], hb[p]);
                hb[p] = fma2(xA2p, p_wi2[p], hb[p]);
            }
        }

        __syncthreads();   // all atomics into s_tot[buf] complete

        // ---- totals: ONE broadcast LDS.128, all lanes get all 4 ----
        float4 tot = *(const float4*)&s_tot[buf][0];
        // zero the buffer for step t+2 (reads of it ended before this bar)
        if (tid < 4) s_tot[buf2][tid] = 0.f;

        const float Sn0 = tot.x, Sn1 = tot.z;
        if (tid == 0 && t > 0) {
            *(float2*)(outp + (size_t)(t - 1) * O_) = make_float2(tot.y, tot.w);
        }

        // ---- stage D: h_{t+1}, tanh, next pr ----
        u64 Sn0p = pack2(Sn0, Sn0);
        u64 Sn1p = pack2(Sn1, Sn1);
        prA = pack2(0.f, 0.f);
        prB = pack2(0.f, 0.f);
#pragma unroll
        for (int p = 0; p < NPAIR; p++) {
            u64 h = fma2(Sn0p, p_m0[p], hb[p]);
            h = fma2(Sn1p, p_m1[p], h);
            hpack[p] = h;
            u64 th = tanh2(h, C_2LOG2E2, C_ONE2, C_NEG22);
            float r0, r1; unpack2(th, r0, r1);
            prA = fma2(pack2(r0, r0), p_n01[2 * p],      prA);
            prB = fma2(pack2(r0, r0), p_wo01[2 * p],     prB);
            prA = fma2(pack2(r1, r1), p_n01[2 * p + 1],  prA);
            prB = fma2(pack2(r1, r1), p_wo01[2 * p + 1], prB);
        }

        z0 = z1; z1 = z2;
        xA0 = xB0; xA1 = xB1; xA2 = xB2;
        xB0 = xC0; xB1 = xC1; xB2 = xC2;
        buf  = (buf  == 2) ? 0 : buf + 1;
        buf2 = (buf2 == 2) ? 0 : buf2 + 1;
    }

    // ---- epilogue: traj[T-1] and out[T-1] ----
    {
        float h0f, h1f, h2f, h3f;
        unpack2(hpack[0], h0f, h1f);
        unpack2(hpack[1], h2f, h3f);
        *(float4*)(trajp + (size_t)(T_ - 1) * H_ + tid * 4) =
            make_float4(h0f, h1f, h2f, h3f);

        float v;
        {
            float px, py, pz, pw;
            unpack2(prA, px, py);
            unpack2(prB, pz, pw);
            const bool k1 = !(lane & 1);
            float sA = k1 ? pz : px;
            float rA = __shfl_xor_sync(FULL, sA, 1);
            float v0 = (k1 ? px : pz) + rA;
            float sB = k1 ? pw : py;
            float rB = __shfl_xor_sync(FULL, sB, 1);
            float v1 = (k1 ? py : pw) + rB;
            const bool k2 = !(lane & 2);
            float sC = k2 ? v1 : v0;
            float rC = __shfl_xor_sync(FULL, sC, 2);
            v = (k2 ? v0 : v1) + rC;
            v += __shfl_xor_sync(FULL, v, 4);
            v += __shfl_xor_sync(FULL, v, 8);
            v += __shfl_xor_sync(FULL, v, 16);
        }
        if (lane < 4) atomicAdd(&s_tot[buf][lane], v);
        __syncthreads();
        if (tid == 0) {
            float4 tot = *(const float4*)&s_tot[buf][0];
            *(float2*)(outp + (size_t)(T_ - 1) * O_) = make_float2(tot.y, tot.w);
        }
    }
}

extern "C" void kernel_launch(void* const* d_in, const int* in_sizes, int n_in,
                              void* d_out, int out_size) {
    (void)in_sizes; (void)n_in; (void)out_size;
    const float* input    = (const float*)d_in[0];
    const float* noise    = (const float*)d_in[1];
    const float* wi       = (const float*)d_in[2];
    const float* unitwi   = (const float*)d_in[3];
    const float* m        = (const float*)d_in[4];
    const float* n        = (const float*)d_in[5];
    const float* unitm    = (const float*)d_in[6];
    const float* unitn    = (const float*)d_in[7];
    const float* wo       = (const float*)d_in[8];
    const float* h0       = (const float*)d_in[9];
    const float* unith0   = (const float*)d_in[10];
    const float* bias     = (const float*)d_in[11];
    const float* gb       = (const float*)d_in[12];
    const float* uv       = (const float*)d_in[13];
    const float* sup      = (const float*)d_in[14];
    float* out            = (float*)d_out;

    lowrank_rnn_kernel<<<B_, NTHREADS>>>(input, noise, wi, unitwi, m, n, unitm,
                                         unitn, wo, h0, unith0, bias, gb, uv,
                                         sup, out);
}

// round 9
// speedup vs baseline: 1.1846x; 1.1846x over previous
#include <cuda_runtime.h>

// Problem constants
#define I_ 3
#define H_ 2048
#define O_ 2
#define R_ 2
#define S_ 4
#define G_ 7
#define B_ 32
#define T_ 512
#define ALPHA_ 0.2f
#define DECAY_ 0.8f
#define NSTD_ 0.05f

#define NTHREADS 512
#define NWARPS (NTHREADS / 32)   // 16
#define EPT 4                    // 512*4 = 2048 = H
#define NPAIR (EPT / 2)

typedef unsigned long long u64;

// ---- f32x2 packed helpers ----
__device__ __forceinline__ u64 pack2(float lo, float hi) {
    u64 r; asm("mov.b64 %0, {%1,%2};" : "=l"(r) : "f"(lo), "f"(hi)); return r;
}
__device__ __forceinline__ void unpack2(u64 v, float& lo, float& hi) {
    asm("mov.b64 {%0,%1}, %2;" : "=f"(lo), "=f"(hi) : "l"(v));
}
__device__ __forceinline__ u64 fma2(u64 a, u64 b, u64 c) {
    u64 d; asm("fma.rn.f32x2 %0, %1, %2, %3;" : "=l"(d) : "l"(a), "l"(b), "l"(c)); return d;
}
__device__ __forceinline__ u64 mul2(u64 a, u64 b) {
    u64 d; asm("mul.rn.f32x2 %0, %1, %2;" : "=l"(d) : "l"(a), "l"(b)); return d;
}
__device__ __forceinline__ u64 add2(u64 a, u64 b) {
    u64 d; asm("add.rn.f32x2 %0, %1, %2;" : "=l"(d) : "l"(a), "l"(b)); return d;
}
__device__ __forceinline__ float ex2f(float x) {
    float y; asm("ex2.approx.f32 %0, %1;" : "=f"(y) : "f"(x)); return y;
}
__device__ __forceinline__ float rcpf(float x) {
    float y; asm("rcp.approx.f32 %0, %1;" : "=f"(y) : "f"(x)); return y;
}
// packed tanh: 1 - 2/(1+exp(2x)) — same precision class as R4-R8 (rel_err 6e-6)
__device__ __forceinline__ u64 tanh2(u64 hp, u64 c_2log2e, u64 c_one, u64 c_neg2) {
    u64 y = mul2(hp, c_2log2e);
    float y0, y1; unpack2(y, y0, y1);
    float e0 = ex2f(y0), e1 = ex2f(y1);
    u64 dp = add2(pack2(e0, e1), c_one);
    float d0, d1; unpack2(dp, d0, d1);
    float r0 = rcpf(d0), r1 = rcpf(d1);
    return fma2(pack2(r0, r1), c_neg2, c_one);
}

__global__ __launch_bounds__(NTHREADS, 1)
void lowrank_rnn_kernel(const float* __restrict__ input,   // (B,T,I)
                        const float* __restrict__ noise,   // (B,T,H)
                        const float* __restrict__ wi,      // (I,S,G)
                        const float* __restrict__ unitwi,  // (I,S,1)
                        const float* __restrict__ m,       // (R,S,G)
                        const float* __restrict__ n,       // (R,S,G)
                        const float* __restrict__ unitm,   // (R,S,1)
                        const float* __restrict__ unitn,   // (R,S,1)
                        const float* __restrict__ wo,      // (O,S,G)
                        const float* __restrict__ h0,      // (S,G)
                        const float* __restrict__ unith0,  // (S,1)
                        const float* __restrict__ bias,    // (S,1)
                        const float* __restrict__ gb,      // (G,H)
                        const float* __restrict__ uv,      // (1,H)
                        const float* __restrict__ sup,     // (S,H)
                        float* __restrict__ out)           // out(B,T,O) ++ traj(B,T,H)
{
    const int b    = blockIdx.x;
    const int tid  = threadIdx.x;
    const int lane = tid & 31;
    const int warp = tid >> 5;
    const unsigned FULL = 0xffffffffu;

    // Channel-separated warp partials, double buffered, 16B aligned.
    // s_n[buf]: [w0.n0, w0.n1, w1.n0, w1.n1, ...]  (32 floats)
    // s_w[buf]: [w0.wo0, w0.wo1, ...]              (32 floats)
    __shared__ __align__(16) float s_n[2][2 * NWARPS];
    __shared__ __align__(16) float s_w[2][2 * NWARPS];

    // ------------------------------------------------------------------
    // Phase 1: per-element effective weights (one-time), then pack.
    // ------------------------------------------------------------------
    float f_h[EPT];
    float f_m0[EPT], f_m1[EPT], f_n0[EPT], f_n1[EPT];
    float f_wo0[EPT], f_wo1[EPT], f_bias[EPT];
    float f_wi0[EPT], f_wi1[EPT], f_wi2[EPT];

#pragma unroll
    for (int e = 0; e < EPT; e++) {
        const int hidx = tid * EPT + e;
        float gvec[G_];
#pragma unroll
        for (int g = 0; g < G_; g++) gvec[g] = gb[g * H_ + hidx];
        const float uvh = uv[hidx];

        float awi0 = 0.f, awi1 = 0.f, awi2 = 0.f;
        float am0 = 0.f, am1 = 0.f, an0 = 0.f, an1 = 0.f;
        float awo0 = 0.f, awo1 = 0.f, ah0 = 0.f, ab = 0.f;

#pragma unroll
        for (int s = 0; s < S_; s++) {
            const float su = sup[s * H_ + hidx];

            float d0 = 0.f, d1 = 0.f, d2 = 0.f;
#pragma unroll
            for (int g = 0; g < G_; g++) {
                d0 += wi[(0 * S_ + s) * G_ + g] * gvec[g];
                d1 += wi[(1 * S_ + s) * G_ + g] * gvec[g];
                d2 += wi[(2 * S_ + s) * G_ + g] * gvec[g];
            }
            awi0 += (d0 + unitwi[0 * S_ + s] * uvh) * su;
            awi1 += (d1 + unitwi[1 * S_ + s] * uvh) * su;
            awi2 += (d2 + unitwi[2 * S_ + s] * uvh) * su;

            float dm0 = 0.f, dm1 = 0.f, dn0 = 0.f, dn1 = 0.f;
#pragma unroll
            for (int g = 0; g < G_; g++) {
                dm0 += m[(0 * S_ + s) * G_ + g] * gvec[g];
                dm1 += m[(1 * S_ + s) * G_ + g] * gvec[g];
                dn0 += n[(0 * S_ + s) * G_ + g] * gvec[g];
                dn1 += n[(1 * S_ + s) * G_ + g] * gvec[g];
            }
            am0 += (dm0 + unitm[0 * S_ + s] * uvh) * su;
            am1 += (dm1 + unitm[1 * S_ + s] * uvh) * su;
            an0 += (dn0 + unitn[0 * S_ + s] * uvh) * su;
            an1 += (dn1 + unitn[1 * S_ + s] * uvh) * su;

            float do0 = 0.f, do1 = 0.f, dh = 0.f;
#pragma unroll
            for (int g = 0; g < G_; g++) {
                do0 += wo[(0 * S_ + s) * G_ + g] * gvec[g];
                do1 += wo[(1 * S_ + s) * G_ + g] * gvec[g];
                dh  += h0[s * G_ + g] * gvec[g];
            }
            awo0 += do0 * su;
            awo1 += do1 * su;
            ah0  += dh * su + unith0[s] * uvh * su;
            ab   += bias[s] * uvh * su;
        }
        f_h[e]   = ah0;
        f_m0[e]  = ALPHA_ * am0;  f_m1[e]  = ALPHA_ * am1;
        f_n0[e]  = an0;           f_n1[e]  = an1;
        f_wo0[e] = awo0;          f_wo1[e] = awo1;
        f_bias[e] = ab;
        f_wi0[e] = ALPHA_ * awi0; f_wi1[e] = ALPHA_ * awi1;
        f_wi2[e] = ALPHA_ * awi2;
    }

    // Packed state/constants
    u64 hpack[NPAIR];
    u64 p_m0[NPAIR], p_m1[NPAIR];
    u64 p_wi0[NPAIR], p_wi1[NPAIR], p_wi2[NPAIR], p_bias[NPAIR];
    u64 p_n01[EPT], p_wo01[EPT];
#pragma unroll
    for (int p = 0; p < NPAIR; p++) {
        hpack[p]  = pack2(f_h[2 * p],   f_h[2 * p + 1]);
        p_m0[p]   = pack2(f_m0[2 * p],  f_m0[2 * p + 1]);
        p_m1[p]   = pack2(f_m1[2 * p],  f_m1[2 * p + 1]);
        p_wi0[p]  = pack2(f_wi0[2 * p], f_wi0[2 * p + 1]);
        p_wi1[p]  = pack2(f_wi1[2 * p], f_wi1[2 * p + 1]);
        p_wi2[p]  = pack2(f_wi2[2 * p], f_wi2[2 * p + 1]);
        p_bias[p] = pack2(f_bias[2 * p], f_bias[2 * p + 1]);
    }
#pragma unroll
    for (int e = 0; e < EPT; e++) {
        p_n01[e]  = pack2(f_n0[e],  f_n1[e]);
        p_wo01[e] = pack2(f_wo0[e], f_wo1[e]);
    }
    const u64 C_DECAY2  = pack2(DECAY_, DECAY_);
    const u64 C_NSTD2   = pack2(NSTD_, NSTD_);
    const u64 C_2LOG2E2 = pack2(2.8853900817779268f, 2.8853900817779268f);
    const u64 C_ONE2    = pack2(1.0f, 1.0f);
    const u64 C_NEG22   = pack2(-2.0f, -2.0f);

    // ------------------------------------------------------------------
    // Phase 2: recurrence.
    //   Loop-top invariant: prA=(Σr·n0, Σr·n1), prB=(Σr·wo0, Σr·wo1) of
    //   r_t = tanh(h_t); hpack = h_t.
    //   Iter t: warp tree -> STS(s_n, s_w); shadow work; bar;
    //   every thread sums s_n via LDS.128 + add2 tree -> (Sn0,Sn1) packed;
    //   warp 0 lazily sums s_w -> out[t-1]; stage D computes next state.
    // ------------------------------------------------------------------
    const float* zb = noise + (size_t)b * T_ * H_;
    const float* xb = input + (size_t)b * T_ * I_;
    float* outp  = out + (size_t)b * T_ * O_;
    float* trajp = out + (size_t)B_ * T_ * O_ + (size_t)b * T_ * H_;

    // Initial pr from r0 = tanh(h0)
    u64 prA = pack2(0.f, 0.f), prB = pack2(0.f, 0.f);
#pragma unroll
    for (int p = 0; p < NPAIR; p++) {
        u64 th = tanh2(hpack[p], C_2LOG2E2, C_ONE2, C_NEG22);
        float r0, r1; unpack2(th, r0, r1);
        prA = fma2(pack2(r0, r0), p_n01[2 * p],      prA);
        prB = fma2(pack2(r0, r0), p_wo01[2 * p],     prB);
        prA = fma2(pack2(r1, r1), p_n01[2 * p + 1],  prA);
        prB = fma2(pack2(r1, r1), p_wo01[2 * p + 1], prB);
    }

    // Prefetch noise / input two steps ahead
    float4 z0 = *(const float4*)(zb + 0 * (size_t)H_ + tid * 4);
    float4 z1 = *(const float4*)(zb + 1 * (size_t)H_ + tid * 4);
    float xA0 = xb[0], xA1 = xb[1], xA2 = xb[2];
    float xB0 = xb[3], xB1 = xb[4], xB2 = xb[5];

    for (int t = 0; t < T_; t++) {
        const int buf = t & 1;

        // ---- stage A: warp-level folded reduce (6 SHFL) ----
        float v;
        {
            float px, py, pz, pw;
            unpack2(prA, px, py);
            unpack2(prB, pz, pw);
            const bool k1 = !(lane & 1);
            float sA = k1 ? pz : px;
            float rA = __shfl_xor_sync(FULL, sA, 1);
            float v0 = (k1 ? px : pz) + rA;
            float sB = k1 ? pw : py;
            float rB = __shfl_xor_sync(FULL, sB, 1);
            float v1 = (k1 ? py : pw) + rB;
            const bool k2 = !(lane & 2);
            float sC = k2 ? v1 : v0;
            float rC = __shfl_xor_sync(FULL, sC, 2);
            v = (k2 ? v0 : v1) + rC;
            v += __shfl_xor_sync(FULL, v, 4);
            v += __shfl_xor_sync(FULL, v, 8);
            v += __shfl_xor_sync(FULL, v, 16);
        }
        // lane 0: n0, lane 1: wo0, lane 2: n1, lane 3: wo1
        if (lane < 4) {
            float* dst = (lane & 1) ? &s_w[buf][0] : &s_n[buf][0];
            dst[2 * warp + (lane >> 1)] = v;
        }

        // ---- shadow: traj store, prefetch, full hb ----
        if (t > 0) {
            float h0f, h1f, h2f, h3f;
            unpack2(hpack[0], h0f, h1f);
            unpack2(hpack[1], h2f, h3f);
            *(float4*)(trajp + (size_t)(t - 1) * H_ + tid * 4) =
                make_float4(h0f, h1f, h2f, h3f);
        }
        const int tp = (t + 2 < T_) ? (t + 2) : (T_ - 1);
        float4 z2 = *(const float4*)(zb + (size_t)tp * H_ + tid * 4);
        const float xC0 = xb[tp * I_ + 0];
        const float xC1 = xb[tp * I_ + 1];
        const float xC2 = xb[tp * I_ + 2];

        u64 hb[NPAIR];
        {
            u64 xA0p = pack2(xA0, xA0);
            u64 xA1p = pack2(xA1, xA1);
            u64 xA2p = pack2(xA2, xA2);
            u64 zp0 = pack2(z0.x, z0.y);
            u64 zp1 = pack2(z0.z, z0.w);
            hb[0] = fma2(hpack[0], C_DECAY2, p_bias[0]);
            hb[0] = fma2(zp0, C_NSTD2, hb[0]);
            hb[1] = fma2(hpack[1], C_DECAY2, p_bias[1]);
            hb[1] = fma2(zp1, C_NSTD2, hb[1]);
#pragma unroll
            for (int p = 0; p < NPAIR; p++) {
                hb[p] = fma2(xA0p, p_wi0[p], hb[p]);
                hb[p] = fma2(xA1p, p_wi1[p], hb[p]);
                hb[p] = fma2(xA2p, p_wi2[p], hb[p]);
            }
        }

        __syncthreads();   // warp partials visible

        // ---- combine: 8x LDS.128 (broadcast) + add2 tree, NO shuffles ----
        u64 SnP;
        {
            const ulonglong2* q = (const ulonglong2*)&s_n[buf][0];  // 8 x (u64,u64)
            ulonglong2 q0 = q[0], q1 = q[1], q2 = q[2], q3 = q[3];
            ulonglong2 q4 = q[4], q5 = q[5], q6 = q[6], q7 = q[7];
            u64 a0 = add2(q0.x, q0.y), a1 = add2(q1.x, q1.y);
            u64 a2 = add2(q2.x, q2.y), a3 = add2(q3.x, q3.y);
            u64 a4 = add2(q4.x, q4.y), a5 = add2(q5.x, q5.y);
            u64 a6 = add2(q6.x, q6.y), a7 = add2(q7.x, q7.y);
            u64 b0 = add2(a0, a1), b1 = add2(a2, a3);
            u64 b2 = add2(a4, a5), b3 = add2(a6, a7);
            SnP = add2(add2(b0, b1), add2(b2, b3));   // (Sn0, Sn1)
        }
        float Sn0, Sn1;
        unpack2(SnP, Sn0, Sn1);

        // ---- stage D: h_{t+1}, tanh, next pr ----
        u64 Sn0p = pack2(Sn0, Sn0);
        u64 Sn1p = pack2(Sn1, Sn1);
        prA = pack2(0.f, 0.f);
        prB = pack2(0.f, 0.f);
#pragma unroll
        for (int p = 0; p < NPAIR; p++) {
            u64 h = fma2(Sn0p, p_m0[p], hb[p]);
            h = fma2(Sn1p, p_m1[p], h);
            hpack[p] = h;
            u64 th = tanh2(h, C_2LOG2E2, C_ONE2, C_NEG22);
            float r0, r1; unpack2(th, r0, r1);
            prA = fma2(pack2(r0, r0), p_n01[2 * p],      prA);
            prB = fma2(pack2(r0, r0), p_wo01[2 * p],     prB);
            prA = fma2(pack2(r1, r1), p_n01[2 * p + 1],  prA);
            prB = fma2(pack2(r1, r1), p_wo01[2 * p + 1], prB);
        }

        // ---- lazy wo combine: warp 0 only, off the critical chain ----
        if (warp == 0 && lane == 0 && t > 0) {
            const ulonglong2* q = (const ulonglong2*)&s_w[buf][0];
            ulonglong2 q0 = q[0], q1 = q[1], q2 = q[2], q3 = q[3];
            ulonglong2 q4 = q[4], q5 = q[5], q6 = q[6], q7 = q[7];
            u64 a0 = add2(q0.x, q0.y), a1 = add2(q1.x, q1.y);
            u64 a2 = add2(q2.x, q2.y), a3 = add2(q3.x, q3.y);
            u64 a4 = add2(q4.x, q4.y), a5 = add2(q5.x, q5.y);
            u64 a6 = add2(q6.x, q6.y), a7 = add2(q7.x, q7.y);
            u64 w = add2(add2(add2(a0, a1), add2(a2, a3)),
                         add2(add2(a4, a5), add2(a6, a7)));
            float o0, o1; unpack2(w, o0, o1);
            *(float2*)(outp + (size_t)(t - 1) * O_) = make_float2(o0, o1);
        }

        z0 = z1; z1 = z2;
        xA0 = xB0; xA1 = xB1; xA2 = xB2;
        xB0 = xC0; xB1 = xC1; xB2 = xC2;
    }

    // ---- epilogue: traj[T-1] and out[T-1] ----
    {
        float h0f, h1f, h2f, h3f;
        unpack2(hpack[0], h0f, h1f);
        unpack2(hpack[1], h2f, h3f);
        *(float4*)(trajp + (size_t)(T_ - 1) * H_ + tid * 4) =
            make_float4(h0f, h1f, h2f, h3f);

        const int buf = T_ & 1;   // 0
        float v;
        {
            float px, py, pz, pw;
            unpack2(prA, px, py);
            unpack2(prB, pz, pw);
            const bool k1 = !(lane & 1);
            float sA = k1 ? pz : px;
            float rA = __shfl_xor_sync(FULL, sA, 1);
            float v0 = (k1 ? px : pz) + rA;
            float sB = k1 ? pw : py;
            float rB = __shfl_xor_sync(FULL, sB, 1);
            float v1 = (k1 ? py : pw) + rB;
            const bool k2 = !(lane & 2);
            float sC = k2 ? v1 : v0;
            float rC = __shfl_xor_sync(FULL, sC, 2);
            v = (k2 ? v0 : v1) + rC;
            v += __shfl_xor_sync(FULL, v, 4);
            v += __shfl_xor_sync(FULL, v, 8);
            v += __shfl_xor_sync(FULL, v, 16);
        }
        if (lane < 4) {
            float* dst = (lane & 1) ? &s_w[buf][0] : &s_n[buf][0];
            dst[2 * warp + (lane >> 1)] = v;
        }
        __syncthreads();
        if (tid == 0) {
            const ulonglong2* q = (const ulonglong2*)&s_w[buf][0];
            ulonglong2 q0 = q[0], q1 = q[1], q2 = q[2], q3 = q[3];
            ulonglong2 q4 = q[4], q5 = q[5], q6 = q[6], q7 = q[7];
            u64 a0 = add2(q0.x, q0.y), a1 = add2(q1.x, q1.y);
            u64 a2 = add2(q2.x, q2.y), a3 = add2(q3.x, q3.y);
            u64 a4 = add2(q4.x, q4.y), a5 = add2(q5.x, q5.y);
            u64 a6 = add2(q6.x, q6.y), a7 = add2(q7.x, q7.y);
            u64 w = add2(add2(add2(a0, a1), add2(a2, a3)),
                         add2(add2(a4, a5), add2(a6, a7)));
            float o0, o1; unpack2(w, o0, o1);
            *(float2*)(outp + (size_t)(T_ - 1) * O_) = make_float2(o0, o1);
        }
    }
}

extern "C" void kernel_launch(void* const* d_in, const int* in_sizes, int n_in,
                              void* d_out, int out_size) {
    (void)in_sizes; (void)n_in; (void)out_size;
    const float* input    = (const float*)d_in[0];
    const float* noise    = (const float*)d_in[1];
    const float* wi       = (const float*)d_in[2];
    const float* unitwi   = (const float*)d_in[3];
    const float* m        = (const float*)d_in[4];
    const float* n        = (const float*)d_in[5];
    const float* unitm    = (const float*)d_in[6];
    const float* unitn    = (const float*)d_in[7];
    const float* wo       = (const float*)d_in[8];
    const float* h0       = (const float*)d_in[9];
    const float* unith0   = (const float*)d_in[10];
    const float* bias     = (const float*)d_in[11];
    const float* gb       = (const float*)d_in[12];
    const float* uv       = (const float*)d_in[13];
    const float* sup      = (const float*)d_in[14];
    float* out            = (float*)d_out;

    lowrank_rnn_kernel<<<B_, NTHREADS>>>(input, noise, wi, unitwi, m, n, unitm,
                                         unitn, wo, h0, unith0, bias, gb, uv,
                                         sup, out);
}

// round 10
// speedup vs baseline: 1.2492x; 1.0545x over previous
#include <cuda_runtime.h>

// Problem constants
#define I_ 3
#define H_ 2048
#define O_ 2
#define R_ 2
#define S_ 4
#define G_ 7
#define B_ 32
#define T_ 512
#define ALPHA_ 0.2f
#define DECAY_ 0.8f
#define NSTD_ 0.05f

#define NTHREADS 256
#define NWARPS (NTHREADS / 32)   // 8
#define EPT 8                    // 256*8 = 2048 = H
#define NPAIR (EPT / 2)          // 4
#define NPART (NWARPS * 4)       // 32 partials per buffer

typedef unsigned long long u64;

// ---- f32x2 packed helpers ----
__device__ __forceinline__ u64 pack2(float lo, float hi) {
    u64 r; asm("mov.b64 %0, {%1,%2};" : "=l"(r) : "f"(lo), "f"(hi)); return r;
}
__device__ __forceinline__ void unpack2(u64 v, float& lo, float& hi) {
    asm("mov.b64 {%0,%1}, %2;" : "=f"(lo), "=f"(hi) : "l"(v));
}
__device__ __forceinline__ u64 fma2(u64 a, u64 b, u64 c) {
    u64 d; asm("fma.rn.f32x2 %0, %1, %2, %3;" : "=l"(d) : "l"(a), "l"(b), "l"(c)); return d;
}
__device__ __forceinline__ u64 mul2(u64 a, u64 b) {
    u64 d; asm("mul.rn.f32x2 %0, %1, %2;" : "=l"(d) : "l"(a), "l"(b)); return d;
}
__device__ __forceinline__ u64 add2(u64 a, u64 b) {
    u64 d; asm("add.rn.f32x2 %0, %1, %2;" : "=l"(d) : "l"(a), "l"(b)); return d;
}
__device__ __forceinline__ float ex2f(float x) {
    float y; asm("ex2.approx.f32 %0, %1;" : "=f"(y) : "f"(x)); return y;
}
__device__ __forceinline__ float rcpf(float x) {
    float y; asm("rcp.approx.f32 %0, %1;" : "=f"(y) : "f"(x)); return y;
}
// packed tanh: 1 - 2/(1+exp(2x)) — same precision class as R4-R9 (rel_err 6e-6)
__device__ __forceinline__ u64 tanh2(u64 hp, u64 c_2log2e, u64 c_one, u64 c_neg2) {
    u64 y = mul2(hp, c_2log2e);
    float y0, y1; unpack2(y, y0, y1);
    float e0 = ex2f(y0), e1 = ex2f(y1);
    u64 dp = add2(pack2(e0, e1), c_one);
    float d0, d1; unpack2(dp, d0, d1);
    float r0 = rcpf(d0), r1 = rcpf(d1);
    return fma2(pack2(r0, r1), c_neg2, c_one);
}

__global__ __launch_bounds__(NTHREADS, 1)
void lowrank_rnn_kernel(const float* __restrict__ input,   // (B,T,I)
                        const float* __restrict__ noise,   // (B,T,H)
                        const float* __restrict__ wi,      // (I,S,G)
                        const float* __restrict__ unitwi,  // (I,S,1)
                        const float* __restrict__ m,       // (R,S,G)
                        const float* __restrict__ n,       // (R,S,G)
                        const float* __restrict__ unitm,   // (R,S,1)
                        const float* __restrict__ unitn,   // (R,S,1)
                        const float* __restrict__ wo,      // (O,S,G)
                        const float* __restrict__ h0,      // (S,G)
                        const float* __restrict__ unith0,  // (S,1)
                        const float* __restrict__ bias,    // (S,1)
                        const float* __restrict__ gb,      // (G,H)
                        const float* __restrict__ uv,      // (1,H)
                        const float* __restrict__ sup,     // (S,H)
                        float* __restrict__ out)           // out(B,T,O) ++ traj(B,T,H)
{
    const int b    = blockIdx.x;
    const int tid  = threadIdx.x;
    const int lane = tid & 31;
    const int warp = tid >> 5;
    const unsigned FULL = 0xffffffffu;

    __shared__ float s_red[2][NPART];   // [warp*4 + ch], ch: 0=n0,1=wo0,2=n1,3=wo1

    // ------------------------------------------------------------------
    // Phase 1: per-element effective weights (one-time), then pack.
    // ------------------------------------------------------------------
    float f_h[EPT];
    float f_m0[EPT], f_m1[EPT], f_n0[EPT], f_n1[EPT];
    float f_wo0[EPT], f_wo1[EPT], f_bias[EPT];
    float f_wi0[EPT], f_wi1[EPT], f_wi2[EPT];

#pragma unroll
    for (int e = 0; e < EPT; e++) {
        const int hidx = tid * EPT + e;
        float gvec[G_];
#pragma unroll
        for (int g = 0; g < G_; g++) gvec[g] = gb[g * H_ + hidx];
        const float uvh = uv[hidx];

        float awi0 = 0.f, awi1 = 0.f, awi2 = 0.f;
        float am0 = 0.f, am1 = 0.f, an0 = 0.f, an1 = 0.f;
        float awo0 = 0.f, awo1 = 0.f, ah0 = 0.f, ab = 0.f;

#pragma unroll
        for (int s = 0; s < S_; s++) {
            const float su = sup[s * H_ + hidx];

            float d0 = 0.f, d1 = 0.f, d2 = 0.f;
#pragma unroll
            for (int g = 0; g < G_; g++) {
                d0 += wi[(0 * S_ + s) * G_ + g] * gvec[g];
                d1 += wi[(1 * S_ + s) * G_ + g] * gvec[g];
                d2 += wi[(2 * S_ + s) * G_ + g] * gvec[g];
            }
            awi0 += (d0 + unitwi[0 * S_ + s] * uvh) * su;
            awi1 += (d1 + unitwi[1 * S_ + s] * uvh) * su;
            awi2 += (d2 + unitwi[2 * S_ + s] * uvh) * su;

            float dm0 = 0.f, dm1 = 0.f, dn0 = 0.f, dn1 = 0.f;
#pragma unroll
            for (int g = 0; g < G_; g++) {
                dm0 += m[(0 * S_ + s) * G_ + g] * gvec[g];
                dm1 += m[(1 * S_ + s) * G_ + g] * gvec[g];
                dn0 += n[(0 * S_ + s) * G_ + g] * gvec[g];
                dn1 += n[(1 * S_ + s) * G_ + g] * gvec[g];
            }
            am0 += (dm0 + unitm[0 * S_ + s] * uvh) * su;
            am1 += (dm1 + unitm[1 * S_ + s] * uvh) * su;
            an0 += (dn0 + unitn[0 * S_ + s] * uvh) * su;
            an1 += (dn1 + unitn[1 * S_ + s] * uvh) * su;

            float do0 = 0.f, do1 = 0.f, dh = 0.f;
#pragma unroll
            for (int g = 0; g < G_; g++) {
                do0 += wo[(0 * S_ + s) * G_ + g] * gvec[g];
                do1 += wo[(1 * S_ + s) * G_ + g] * gvec[g];
                dh  += h0[s * G_ + g] * gvec[g];
            }
            awo0 += do0 * su;
            awo1 += do1 * su;
            ah0  += dh * su + unith0[s] * uvh * su;
            ab   += bias[s] * uvh * su;
        }
        f_h[e]   = ah0;
        f_m0[e]  = ALPHA_ * am0;  f_m1[e]  = ALPHA_ * am1;
        f_n0[e]  = an0;           f_n1[e]  = an1;
        f_wo0[e] = awo0;          f_wo1[e] = awo1;
        f_bias[e] = ab;
        f_wi0[e] = ALPHA_ * awi0; f_wi1[e] = ALPHA_ * awi1;
        f_wi2[e] = ALPHA_ * awi2;
    }

    // Packed state/constants
    u64 hpack[NPAIR];
    u64 p_m0[NPAIR], p_m1[NPAIR];
    u64 p_wi0[NPAIR], p_wi1[NPAIR], p_wi2[NPAIR], p_bias[NPAIR];
    u64 p_n01[EPT], p_wo01[EPT];
#pragma unroll
    for (int p = 0; p < NPAIR; p++) {
        hpack[p]  = pack2(f_h[2 * p],   f_h[2 * p + 1]);
        p_m0[p]   = pack2(f_m0[2 * p],  f_m0[2 * p + 1]);
        p_m1[p]   = pack2(f_m1[2 * p],  f_m1[2 * p + 1]);
        p_wi0[p]  = pack2(f_wi0[2 * p], f_wi0[2 * p + 1]);
        p_wi1[p]  = pack2(f_wi1[2 * p], f_wi1[2 * p + 1]);
        p_wi2[p]  = pack2(f_wi2[2 * p], f_wi2[2 * p + 1]);
        p_bias[p] = pack2(f_bias[2 * p], f_bias[2 * p + 1]);
    }
#pragma unroll
    for (int e = 0; e < EPT; e++) {
        p_n01[e]  = pack2(f_n0[e],  f_n1[e]);
        p_wo01[e] = pack2(f_wo0[e], f_wo1[e]);
    }
    const u64 C_DECAY2  = pack2(DECAY_, DECAY_);
    const u64 C_NSTD2   = pack2(NSTD_, NSTD_);
    const u64 C_2LOG2E2 = pack2(2.8853900817779268f, 2.8853900817779268f);
    const u64 C_ONE2    = pack2(1.0f, 1.0f);
    const u64 C_NEG22   = pack2(-2.0f, -2.0f);

    // ------------------------------------------------------------------
    // Phase 2: recurrence.
    //   Loop-top invariant: prA=(Σr·n0, Σr·n1), prB=(Σr·wo0, Σr·wo1) of
    //   r_t = tanh(h_t); hpack = h_t.
    //   Iter t: 6-SHFL folded warp tree -> lanes 0-3 STS; shadow work; bar;
    //   1 LDS.32 + 3-SHFL butterfly + 2 broadcasts -> Sn; stage D.
    // ------------------------------------------------------------------
    const float* zb = noise + (size_t)b * T_ * H_;
    const float* xb = input + (size_t)b * T_ * I_;
    float* outp  = out + (size_t)b * T_ * O_;
    float* trajp = out + (size_t)B_ * T_ * O_ + (size_t)b * T_ * H_;

    // Initial pr from r0 = tanh(h0)
    u64 prA = pack2(0.f, 0.f), prB = pack2(0.f, 0.f);
#pragma unroll
    for (int p = 0; p < NPAIR; p++) {
        u64 th = tanh2(hpack[p], C_2LOG2E2, C_ONE2, C_NEG22);
        float r0, r1; unpack2(th, r0, r1);
        prA = fma2(pack2(r0, r0), p_n01[2 * p],      prA);
        prB = fma2(pack2(r0, r0), p_wo01[2 * p],     prB);
        prA = fma2(pack2(r1, r1), p_n01[2 * p + 1],  prA);
        prB = fma2(pack2(r1, r1), p_wo01[2 * p + 1], prB);
    }

    // Prefetch noise / input (double-buffered, one step ahead)
    float4 z0a = *(const float4*)(zb + 0 * (size_t)H_ + tid * EPT);
    float4 z0b = *(const float4*)(zb + 0 * (size_t)H_ + tid * EPT + 4);
    float4 z1a = *(const float4*)(zb + 1 * (size_t)H_ + tid * EPT);
    float4 z1b = *(const float4*)(zb + 1 * (size_t)H_ + tid * EPT + 4);
    float xA0 = xb[0], xA1 = xb[1], xA2 = xb[2];
    float xB0 = xb[3], xB1 = xb[4], xB2 = xb[5];

    for (int t = 0; t < T_; t++) {
        const int buf = t & 1;

        // ---- stage A: warp-level folded reduce (6 SHFL) ----
        float v;
        {
            float px, py, pz, pw;
            unpack2(prA, px, py);
            unpack2(prB, pz, pw);
            const bool k1 = !(lane & 1);
            float sA = k1 ? pz : px;
            float rA = __shfl_xor_sync(FULL, sA, 1);
            float v0 = (k1 ? px : pz) + rA;
            float sB = k1 ? pw : py;
            float rB = __shfl_xor_sync(FULL, sB, 1);
            float v1 = (k1 ? py : pw) + rB;
            const bool k2 = !(lane & 2);
            float sC = k2 ? v1 : v0;
            float rC = __shfl_xor_sync(FULL, sC, 2);
            v = (k2 ? v0 : v1) + rC;
            v += __shfl_xor_sync(FULL, v, 4);
            v += __shfl_xor_sync(FULL, v, 8);
            v += __shfl_xor_sync(FULL, v, 16);
        }
        // lane&3: 0 -> n0, 1 -> wo0, 2 -> n1, 3 -> wo1
        if (lane < 4) s_red[buf][warp * 4 + lane] = v;

        // ---- shadow: traj store, prefetch, full hb ----
        if (t > 0) {
            float h0f, h1f, h2f, h3f, h4f, h5f, h6f, h7f;
            unpack2(hpack[0], h0f, h1f);
            unpack2(hpack[1], h2f, h3f);
            unpack2(hpack[2], h4f, h5f);
            unpack2(hpack[3], h6f, h7f);
            *(float4*)(trajp + (size_t)(t - 1) * H_ + tid * EPT) =
                make_float4(h0f, h1f, h2f, h3f);
            *(float4*)(trajp + (size_t)(t - 1) * H_ + tid * EPT + 4) =
                make_float4(h4f, h5f, h6f, h7f);
        }
        const int tp = (t + 2 < T_) ? (t + 2) : (T_ - 1);
        float4 z2a = *(const float4*)(zb + (size_t)tp * H_ + tid * EPT);
        float4 z2b = *(const float4*)(zb + (size_t)tp * H_ + tid * EPT + 4);
        const float xC0 = xb[tp * I_ + 0];
        const float xC1 = xb[tp * I_ + 1];
        const float xC2 = xb[tp * I_ + 2];

        u64 hb[NPAIR];
        {
            u64 xA0p = pack2(xA0, xA0);
            u64 xA1p = pack2(xA1, xA1);
            u64 xA2p = pack2(xA2, xA2);
            u64 zp[NPAIR];
            zp[0] = pack2(z0a.x, z0a.y);
            zp[1] = pack2(z0a.z, z0a.w);
            zp[2] = pack2(z0b.x, z0b.y);
            zp[3] = pack2(z0b.z, z0b.w);
#pragma unroll
            for (int p = 0; p < NPAIR; p++) {
                u64 t0 = fma2(hpack[p], C_DECAY2, p_bias[p]);
                t0 = fma2(zp[p], C_NSTD2, t0);
                t0 = fma2(xA0p, p_wi0[p], t0);
                t0 = fma2(xA1p, p_wi1[p], t0);
                hb[p] = fma2(xA2p, p_wi2[p], t0);
            }
        }

        __syncthreads();   // warp partials visible

        // ---- stage C: 1 LDS.32 + 3-SHFL butterfly over warps ----
        float u = s_red[buf][lane];            // [w][c], lane = w*4+c (8 warps)
        u += __shfl_xor_sync(FULL, u, 4);
        u += __shfl_xor_sync(FULL, u, 8);
        u += __shfl_xor_sync(FULL, u, 16);
        // lane&3: 0 -> n0, 1 -> wo0, 2 -> n1, 3 -> wo1 (block totals)
        float Sn0 = __shfl_sync(FULL, u, 0);
        float Sn1 = __shfl_sync(FULL, u, 2);
        if (warp == 0 && t > 0) {
            if (lane == 1) outp[(t - 1) * O_ + 0] = u;
            if (lane == 3) outp[(t - 1) * O_ + 1] = u;
        }

        // ---- stage D: h_{t+1}, tanh, next pr ----
        u64 Sn0p = pack2(Sn0, Sn0);
        u64 Sn1p = pack2(Sn1, Sn1);
        prA = pack2(0.f, 0.f);
        prB = pack2(0.f, 0.f);
#pragma unroll
        for (int p = 0; p < NPAIR; p++) {
            u64 h = fma2(Sn0p, p_m0[p], hb[p]);
            h = fma2(Sn1p, p_m1[p], h);
            hpack[p] = h;
            u64 th = tanh2(h, C_2LOG2E2, C_ONE2, C_NEG22);
            float r0, r1; unpack2(th, r0, r1);
            prA = fma2(pack2(r0, r0), p_n01[2 * p],      prA);
            prB = fma2(pack2(r0, r0), p_wo01[2 * p],     prB);
            prA = fma2(pack2(r1, r1), p_n01[2 * p + 1],  prA);
            prB = fma2(pack2(r1, r1), p_wo01[2 * p + 1], prB);
        }

        z0a = z1a; z0b = z1b;
        z1a = z2a; z1b = z2b;
        xA0 = xB0; xA1 = xB1; xA2 = xB2;
        xB0 = xC0; xB1 = xC1; xB2 = xC2;
    }

    // ---- epilogue: traj[T-1] and out[T-1] ----
    {
        float h0f, h1f, h2f, h3f, h4f, h5f, h6f, h7f;
        unpack2(hpack[0], h0f, h1f);
        unpack2(hpack[1], h2f, h3f);
        unpack2(hpack[2], h4f, h5f);
        unpack2(hpack[3], h6f, h7f);
        *(float4*)(trajp + (size_t)(T_ - 1) * H_ + tid * EPT) =
            make_float4(h0f, h1f, h2f, h3f);
        *(float4*)(trajp + (size_t)(T_ - 1) * H_ + tid * EPT + 4) =
            make_float4(h4f, h5f, h6f, h7f);

        const int buf = T_ & 1;   // 0
        float v;
        {
            float px, py, pz, pw;
            unpack2(prA, px, py);
            unpack2(prB, pz, pw);
            const bool k1 = !(lane & 1);
            float sA = k1 ? pz : px;
            float rA = __shfl_xor_sync(FULL, sA, 1);
            float v0 = (k1 ? px : pz) + rA;
            float sB = k1 ? pw : py;
            float rB = __shfl_xor_sync(FULL, sB, 1);
            float v1 = (k1 ? py : pw) + rB;
            const bool k2 = !(lane & 2);
            float sC = k2 ? v1 : v0;
            float rC = __shfl_xor_sync(FULL, sC, 2);
            v = (k2 ? v0 : v1) + rC;
            v += __shfl_xor_sync(FULL, v, 4);
            v += __shfl_xor_sync(FULL, v, 8);
            v += __shfl_xor_sync(FULL, v, 16);
        }
        if (lane < 4) s_red[buf][warp * 4 + lane] = v;
        __syncthreads();
        if (warp == 0) {
            float u = s_red[buf][lane];
            u += __shfl_xor_sync(FULL, u, 4);
            u += __shfl_xor_sync(FULL, u, 8);
            u += __shfl_xor_sync(FULL, u, 16);
            if (lane == 1) outp[(T_ - 1) * O_ + 0] = u;
            if (lane == 3) outp[(T_ - 1) * O_ + 1] = u;
        }
    }
}

extern "C" void kernel_launch(void* const* d_in, const int* in_sizes, int n_in,
                              void* d_out, int out_size) {
    (void)in_sizes; (void)n_in; (void)out_size;
    const float* input    = (const float*)d_in[0];
    const float* noise    = (const float*)d_in[1];
    const float* wi       = (const float*)d_in[2];
    const float* unitwi   = (const float*)d_in[3];
    const float* m        = (const float*)d_in[4];
    const float* n        = (const float*)d_in[5];
    const float* unitm    = (const float*)d_in[6];
    const float* unitn    = (const float*)d_in[7];
    const float* wo       = (const float*)d_in[8];
    const float* h0       = (const float*)d_in[9];
    const float* unith0   = (const float*)d_in[10];
    const float* bias     = (const float*)d_in[11];
    const float* gb       = (const float*)d_in[12];
    const float* uv       = (const float*)d_in[13];
    const float* sup      = (const float*)d_in[14];
    float* out            = (float*)d_out;

    lowrank_rnn_kernel<<<B_, NTHREADS>>>(input, noise, wi, unitwi, m, n, unitm,
                                         unitn, wo, h0, unith0, bias, gb, uv,
                                         sup, out);
}